// round 1
// baseline (speedup 1.0000x reference)
#include <cuda_runtime.h>

// SoftMaxPlus: out[b, :] = cumsum(softplus(beta * c[b, :]) / beta) along S.
// B=4096 rows, S=8192 cols, fp32. One CTA per row, 1024 threads x 8 elems.

constexpr int S_LEN  = 8192;
constexpr int NTHREADS = 1024;
constexpr int EPT = S_LEN / NTHREADS;   // 8 elements per thread
constexpr int NWARPS = NTHREADS / 32;   // 32

__global__ __launch_bounds__(NTHREADS, 1)
void softmaxplus_scan_kernel(const float* __restrict__ c,
                             const float* __restrict__ beta_ptr,
                             float* __restrict__ out)
{
    const float beta = beta_ptr[0];
    const float inv_beta = 1.0f / beta;

    const long long row = blockIdx.x;
    const float* row_in  = c   + row * (long long)S_LEN;
    float*       row_out = out + row * (long long)S_LEN;

    const int t = threadIdx.x;

    // ---- load 8 contiguous floats (two float4) ----
    const float4* in4 = reinterpret_cast<const float4*>(row_in) + t * 2;
    float4 a = in4[0];
    float4 b = in4[1];

    float v[EPT] = {a.x, a.y, a.z, a.w, b.x, b.y, b.z, b.w};

    // ---- elementwise: softplus(beta*x)/beta, overflow-safe ----
#pragma unroll
    for (int i = 0; i < EPT; i++) {
        float x  = beta * v[i];
        float sp = fmaxf(x, 0.0f) + log1pf(__expf(-fabsf(x)));
        v[i] = sp * inv_beta;
    }

    // ---- inclusive prefix within thread ----
#pragma unroll
    for (int i = 1; i < EPT; i++) v[i] += v[i - 1];
    const float tsum = v[EPT - 1];

    // ---- inclusive warp scan of per-thread sums ----
    const int lane = t & 31;
    const int wid  = t >> 5;
    float ws = tsum;
#pragma unroll
    for (int o = 1; o < 32; o <<= 1) {
        float y = __shfl_up_sync(0xFFFFFFFFu, ws, o);
        if (lane >= o) ws += y;
    }
    // exclusive offset for this thread within its warp:
    const float thread_excl = ws - tsum;

    // ---- scan the 32 warp totals ----
    __shared__ float warp_incl[NWARPS];
    if (lane == 31) warp_incl[wid] = ws;   // warp's inclusive total
    __syncthreads();

    if (wid == 0) {
        float w = warp_incl[lane];
#pragma unroll
        for (int o = 1; o < 32; o <<= 1) {
            float y = __shfl_up_sync(0xFFFFFFFFu, w, o);
            if (lane >= o) w += y;
        }
        warp_incl[lane] = w;               // inclusive scan of warp totals
    }
    __syncthreads();

    const float warp_excl = (wid > 0) ? warp_incl[wid - 1] : 0.0f;
    const float offset = warp_excl + thread_excl;

    // ---- add offsets and store (two float4) ----
    float4 o0 = make_float4(v[0] + offset, v[1] + offset, v[2] + offset, v[3] + offset);
    float4 o1 = make_float4(v[4] + offset, v[5] + offset, v[6] + offset, v[7] + offset);

    float4* out4 = reinterpret_cast<float4*>(row_out) + t * 2;
    out4[0] = o0;
    out4[1] = o1;
}

extern "C" void kernel_launch(void* const* d_in, const int* in_sizes, int n_in,
                              void* d_out, int out_size)
{
    const float* c    = (const float*)d_in[0];
    const float* beta = (const float*)d_in[1];
    float* out        = (float*)d_out;

    const int B = in_sizes[0] / S_LEN;  // 4096
    softmaxplus_scan_kernel<<<B, NTHREADS>>>(c, beta, out);
}

// round 2
// speedup vs baseline: 1.6425x; 1.6425x over previous
#include <cuda_runtime.h>

// SoftMaxPlus: out[b, :] = cumsum(softplus(beta * c[b, :]) / beta) along S.
// B=4096 rows, S=8192 cols, fp32.
// 512 threads/CTA, 2 CTAs/SM, 4 rows per CTA with next-row prefetch.
// Layout: warp w owns segments [w*4, w*4+4) of 128 elems each; thread lane l
// loads float4 at seg*128 + l*4  -> every LDG.128/STG.128 perfectly coalesced.

constexpr int S_LEN        = 8192;
constexpr int NTHREADS     = 512;
constexpr int NWARPS       = 16;
constexpr int GROUPS       = 4;     // float4 groups (segments) per thread
constexpr int ROWS_PER_CTA = 4;

struct RowBuf { float4 g[GROUPS]; };

__device__ __forceinline__ void load_row(RowBuf& rb, const float* __restrict__ row,
                                         int w, int l)
{
#pragma unroll
    for (int g = 0; g < GROUPS; g++) {
        const int seg = w * GROUPS + g;
        rb.g[g] = *reinterpret_cast<const float4*>(row + seg * 128 + l * 4);
    }
}

// softplus(beta*c)/beta = max(c,0) + log2(1 + exp2(kE*|c|)) * kL
//   kE = -beta*log2(e), kL = ln2/beta
__device__ __forceinline__ float sp_fast(float c, float kE, float kL)
{
    float t = exp2f(kE * fabsf(c));                 // FMUL + MUFU.EX2
    return fmaxf(c, 0.0f) + __log2f(1.0f + t) * kL; // FMNMX + FADD + MUFU.LG2 + FFMA
}

__device__ __forceinline__ void process_row(const RowBuf& rb, float* __restrict__ rowout,
                                            int w, int l, float kE, float kL,
                                            float* __restrict__ tot /* NWARPS floats */)
{
    float p[GROUPS][4];
    float texcl[GROUPS];
    float gtot[GROUPS];

#pragma unroll
    for (int g = 0; g < GROUPS; g++) {
        const float4 v = rb.g[g];
        float f0 = sp_fast(v.x, kE, kL);
        float f1 = sp_fast(v.y, kE, kL);
        float f2 = sp_fast(v.z, kE, kL);
        float f3 = sp_fast(v.w, kE, kL);
        // inclusive prefix within the 4
        p[g][0] = f0;
        p[g][1] = p[g][0] + f1;
        p[g][2] = p[g][1] + f2;
        p[g][3] = p[g][2] + f3;
        // inclusive warp scan of per-thread 4-sums
        float ws = p[g][3];
#pragma unroll
        for (int o = 1; o < 32; o <<= 1) {
            float y = __shfl_up_sync(0xFFFFFFFFu, ws, o);
            if (l >= o) ws += y;
        }
        texcl[g] = ws - p[g][3];                       // exclusive offset in segment
        gtot[g]  = __shfl_sync(0xFFFFFFFFu, ws, 31);   // segment total
    }

    // exclusive offsets of the 4 segments inside this warp's 512-elem span
    const float ge1 = gtot[0];
    const float ge2 = ge1 + gtot[1];
    const float ge3 = ge2 + gtot[2];
    const float wtot = ge3 + gtot[3];

    if (l == 0) tot[w] = wtot;
    __syncthreads();

    // exclusive sum of warp totals for warps < w, via masked butterfly reduce
    float x = (l < NWARPS) ? tot[l] : 0.0f;
    float m = (l < w) ? x : 0.0f;
#pragma unroll
    for (int o = 16; o >= 1; o >>= 1)
        m += __shfl_xor_sync(0xFFFFFFFFu, m, o);
    // m == sum of tot[0..w-1] on every lane

    const float off0 = m;
    const float off1 = m + ge1;
    const float off2 = m + ge2;
    const float off3 = m + ge3;
    const float offs[GROUPS] = {off0, off1, off2, off3};

#pragma unroll
    for (int g = 0; g < GROUPS; g++) {
        const int seg = w * GROUPS + g;
        const float o = offs[g] + texcl[g];
        float4 r = make_float4(p[g][0] + o, p[g][1] + o, p[g][2] + o, p[g][3] + o);
        *reinterpret_cast<float4*>(rowout + seg * 128 + l * 4) = r;
    }
}

__global__ __launch_bounds__(NTHREADS, 2)
void softmaxplus_scan_kernel(const float* __restrict__ c,
                             const float* __restrict__ beta_ptr,
                             float* __restrict__ out)
{
    __shared__ float tot[2][NWARPS];

    const int t = threadIdx.x;
    const int w = t >> 5;
    const int l = t & 31;

    const float beta     = beta_ptr[0];
    const float inv_beta = 1.0f / beta;
    const float kE = -beta * 1.4426950408889634f;   // -beta*log2(e)
    const float kL = 0.6931471805599453f * inv_beta; // ln2/beta

    const long long base = (long long)blockIdx.x * ROWS_PER_CTA;
    const float* in0  = c   + base * S_LEN;
    float*       out0 = out + base * S_LEN;

    RowBuf A, B;
    load_row(A, in0, w, l);                        // row 0
    load_row(B, in0 + S_LEN, w, l);                // prefetch row 1
    process_row(A, out0, w, l, kE, kL, tot[0]);

    load_row(A, in0 + 2 * S_LEN, w, l);            // prefetch row 2
    process_row(B, out0 + S_LEN, w, l, kE, kL, tot[1]);

    load_row(B, in0 + 3 * S_LEN, w, l);            // prefetch row 3
    process_row(A, out0 + 2 * S_LEN, w, l, kE, kL, tot[0]);

    process_row(B, out0 + 3 * S_LEN, w, l, kE, kL, tot[1]);
}

extern "C" void kernel_launch(void* const* d_in, const int* in_sizes, int n_in,
                              void* d_out, int out_size)
{
    const float* c    = (const float*)d_in[0];
    const float* beta = (const float*)d_in[1];
    float* out        = (float*)d_out;

    const int B = in_sizes[0] / S_LEN;             // 4096
    softmaxplus_scan_kernel<<<B / ROWS_PER_CTA, NTHREADS>>>(c, beta, out);
}

// round 5
// speedup vs baseline: 1.8389x; 1.1196x over previous
#include <cuda_runtime.h>

// SoftMaxPlus: out[b, :] = cumsum(softplus(beta * c[b, :]) / beta) along S.
// B=4096 rows, S=8192 cols, fp32.
// Persistent grid (304 CTAs = 152 SMs x 2), 512 thr/CTA, grid-stride over rows.
// Depth-3 cp.async smem ring: >=2 rows (64KB) always in flight per CTA.
// Each thread async-copies exactly the bytes it later reads -> no extra barriers.

constexpr int S_LEN    = 8192;
constexpr int NTHREADS = 512;
constexpr int NWARPS   = 16;
constexpr int GROUPS   = 4;          // 4 float4 (segments) per thread
constexpr int DEPTH    = 3;          // smem ring depth (rows)
constexpr int GRID     = 304;        // 152 SMs x 2 CTAs/SM

__device__ __forceinline__ void cp16(float* smem_dst, const float* gsrc)
{
    unsigned s = (unsigned)__cvta_generic_to_shared(smem_dst);
    asm volatile("cp.async.cg.shared.global [%0], [%1], 16;\n" :: "r"(s), "l"(gsrc));
}

__device__ __forceinline__ void prefetch_row(float* slot, const float* row,
                                             bool valid, int w, int l)
{
    if (valid) {
#pragma unroll
        for (int g = 0; g < GROUPS; g++) {
            const int idx = ((w * GROUPS + g) * 32 + l) * 4;   // float index
            cp16(slot + idx, row + idx);
        }
    }
    asm volatile("cp.async.commit_group;\n" ::: "memory");     // always a group
}

// softplus(beta*c)/beta = max(c,0) + log2(1 + exp2(kE*|c|)) * kL
__device__ __forceinline__ float sp_fast(float c, float kE, float kL)
{
    float t = exp2f(kE * fabsf(c));
    return fmaxf(c, 0.0f) + __log2f(1.0f + t) * kL;
}

extern __shared__ float ring[];      // DEPTH * S_LEN floats (96 KB)

__global__ __launch_bounds__(NTHREADS, 2)
void softmaxplus_scan_kernel(const float* __restrict__ c,
                             const float* __restrict__ beta_ptr,
                             float* __restrict__ out,
                             int nrows)
{
    __shared__ float tot[2][NWARPS];

    const int t = threadIdx.x;
    const int w = t >> 5;
    const int l = t & 31;
    const int grid = gridDim.x;

    const float beta = __ldg(beta_ptr);
    const float kE = -beta * 1.4426950408889634f;          // -beta*log2(e)
    const float kL = 0.6931471805599453f / beta;           // ln2/beta

    // ---- prologue: prefetch rows r0, r0+grid, r0+2*grid ----
#pragma unroll
    for (int d = 0; d < DEPTH; d++) {
        const long long rr = blockIdx.x + (long long)d * grid;
        prefetch_row(ring + d * S_LEN, c + rr * S_LEN, rr < nrows, w, l);
    }

    int it = 0;
    int slot = 0;
    for (long long r = blockIdx.x; r < nrows; r += grid, it++) {
        // group for row r is complete once <= DEPTH-1 groups are outstanding
        asm volatile("cp.async.wait_group %0;\n" :: "n"(DEPTH - 1) : "memory");

        const float* sbuf = ring + slot * S_LEN;
        float*       rowout = out + r * (long long)S_LEN;

        // ---- read own 16 floats from smem ----
        float4 vv[GROUPS];
#pragma unroll
        for (int g = 0; g < GROUPS; g++)
            vv[g] = *reinterpret_cast<const float4*>(sbuf + ((w * GROUPS + g) * 32 + l) * 4);

        // ---- elementwise + per-thread prefix + warp scans ----
        float p[GROUPS][4];
        float texcl[GROUPS];
        float gtot[GROUPS];
#pragma unroll
        for (int g = 0; g < GROUPS; g++) {
            float f0 = sp_fast(vv[g].x, kE, kL);
            float f1 = sp_fast(vv[g].y, kE, kL);
            float f2 = sp_fast(vv[g].z, kE, kL);
            float f3 = sp_fast(vv[g].w, kE, kL);
            p[g][0] = f0;
            p[g][1] = p[g][0] + f1;
            p[g][2] = p[g][1] + f2;
            p[g][3] = p[g][2] + f3;
            float ws = p[g][3];
#pragma unroll
            for (int o = 1; o < 32; o <<= 1) {
                float y = __shfl_up_sync(0xFFFFFFFFu, ws, o);
                if (l >= o) ws += y;
            }
            texcl[g] = ws - p[g][3];
            gtot[g]  = __shfl_sync(0xFFFFFFFFu, ws, 31);
        }

        // vv[] fully consumed -> safe to reuse this smem slot for row r+DEPTH*grid
        {
            const long long rn = r + (long long)DEPTH * grid;
            prefetch_row(ring + slot * S_LEN, c + rn * S_LEN, rn < nrows, w, l);
        }

        // ---- segment offsets within this warp's 512-elem span ----
        const float ge1 = gtot[0];
        const float ge2 = ge1 + gtot[1];
        const float ge3 = ge2 + gtot[2];
        const float wtot = ge3 + gtot[3];

        float* tb = tot[it & 1];
        if (l == 0) tb[w] = wtot;
        __syncthreads();

        // exclusive sum of warp totals for warps < w (masked butterfly)
        float m = (l < w) ? tb[l] : 0.0f;
#pragma unroll
        for (int o = 16; o >= 1; o >>= 1)
            m += __shfl_xor_sync(0xFFFFFFFFu, m, o);

        const float offs[GROUPS] = {m, m + ge1, m + ge2, m + ge3};

        // ---- add offsets and stream out ----
#pragma unroll
        for (int g = 0; g < GROUPS; g++) {
            const float o = offs[g] + texcl[g];
            float4 rv = make_float4(p[g][0] + o, p[g][1] + o, p[g][2] + o, p[g][3] + o);
            __stcs(reinterpret_cast<float4*>(rowout + ((w * GROUPS + g) * 32 + l) * 4), rv);
        }

        slot = (slot == DEPTH - 1) ? 0 : slot + 1;
    }
}

extern "C" void kernel_launch(void* const* d_in, const int* in_sizes, int n_in,
                              void* d_out, int out_size)
{
    const float* c    = (const float*)d_in[0];
    const float* beta = (const float*)d_in[1];
    float* out        = (float*)d_out;

    const int nrows = in_sizes[0] / S_LEN;   // 4096
    const int smem_bytes = DEPTH * S_LEN * sizeof(float);  // 96 KB

    static bool attr_set = false;
    if (!attr_set) {
        cudaFuncSetAttribute(softmaxplus_scan_kernel,
                             cudaFuncAttributeMaxDynamicSharedMemorySize, smem_bytes);
        attr_set = true;
    }

    softmaxplus_scan_kernel<<<GRID, NTHREADS, smem_bytes>>>(c, beta, out, nrows);
}

// round 7
// speedup vs baseline: 1.8400x; 1.0006x over previous
#include <cuda_runtime.h>

// SoftMaxPlus: out[b, :] = cumsum(softplus(beta * c[b, :]) / beta) along S.
// B=4096 rows, S=8192 cols, fp32.
// Warp-autonomous: each warp owns one row (atomic ticket for perfect balance).
// Row processed as 16 chunks of 512 elems, register ping-pong pipeline.
// No barriers, no shared memory. All LDG.128/STG.128 fully coalesced.

constexpr int S_LEN    = 8192;
constexpr int NTHREADS = 512;          // 16 warps per CTA
constexpr int CHUNK    = 512;          // elems per warp-chunk
constexpr int NCHUNK   = S_LEN / CHUNK; // 16
constexpr int GRID     = 304;          // 152 SMs x 2 CTAs

__device__ unsigned g_ticket;

__global__ void reset_ticket_kernel() { g_ticket = 0u; }

// softplus(beta*c)/beta = max(c,0) + log2(1 + exp2(kE*|c|)) * kL
__device__ __forceinline__ float sp_fast(float c, float kE, float kL)
{
    float t = exp2f(kE * fabsf(c));
    return fmaxf(c, 0.0f) + __log2f(1.0f + t) * kL;
}

// Load chunk k: 4 coalesced float4s (segment layout: seg j, lane l -> j*128+l*4)
__device__ __forceinline__ void load_chunk(float4 v[4], const float* __restrict__ rowc,
                                           int k, int l)
{
#pragma unroll
    for (int j = 0; j < 4; j++)
        v[j] = __ldcs(reinterpret_cast<const float4*>(rowc + k * CHUNK + j * 128 + l * 4));
}

// Scan chunk in place: softplus + prefix + 4 segment warp-scans + store. Returns new carry.
__device__ __forceinline__ float scan_chunk(float4 v[4], float* __restrict__ rowout,
                                            int k, int l, float kE, float kL, float carry)
{
    float gt[4], tx[4];
#pragma unroll
    for (int j = 0; j < 4; j++) {
        float f0 = sp_fast(v[j].x, kE, kL);
        float f1 = sp_fast(v[j].y, kE, kL);
        float f2 = sp_fast(v[j].z, kE, kL);
        float f3 = sp_fast(v[j].w, kE, kL);
        v[j].x = f0;
        v[j].y = v[j].x + f1;
        v[j].z = v[j].y + f2;
        v[j].w = v[j].z + f3;
        // inclusive warp scan of per-lane 4-sums
        float ws = v[j].w;
#pragma unroll
        for (int o = 1; o < 32; o <<= 1) {
            float y = __shfl_up_sync(0xFFFFFFFFu, ws, o);
            if (l >= o) ws += y;
        }
        tx[j] = ws - v[j].w;                         // exclusive offset in segment
        gt[j] = __shfl_sync(0xFFFFFFFFu, ws, 31);    // segment total (all lanes)
    }

    float e = carry;
#pragma unroll
    for (int j = 0; j < 4; j++) {
        const float o = e + tx[j];
        float4 r = make_float4(v[j].x + o, v[j].y + o, v[j].z + o, v[j].w + o);
        __stcs(reinterpret_cast<float4*>(rowout + k * CHUNK + j * 128 + l * 4), r);
        e += gt[j];
    }
    return e;
}

__global__ __launch_bounds__(NTHREADS, 2)
void softmaxplus_scan_kernel(const float* __restrict__ c,
                             const float* __restrict__ beta_ptr,
                             float* __restrict__ out,
                             int nrows)
{
    const int l = threadIdx.x & 31;

    const float beta = __ldg(beta_ptr);
    const float kE = -beta * 1.4426950408889634f;    // -beta*log2(e)
    const float kL = 0.6931471805599453f / beta;     // ln2/beta

    for (;;) {
        unsigned row = 0u;
        if (l == 0) row = atomicAdd(&g_ticket, 1u);
        row = __shfl_sync(0xFFFFFFFFu, row, 0);
        if (row >= (unsigned)nrows) break;

        const float* rowc   = c   + (long long)row * S_LEN;
        float*       rowout = out + (long long)row * S_LEN;

        float4 a[4], b[4];
        float carry = 0.0f;

        load_chunk(a, rowc, 0, l);
#pragma unroll 1
        for (int k = 0; k < NCHUNK; k += 2) {
            load_chunk(b, rowc, k + 1, l);           // prefetch odd chunk
            carry = scan_chunk(a, rowout, k, l, kE, kL, carry);
            if (k + 2 < NCHUNK) load_chunk(a, rowc, k + 2, l);  // prefetch next even
            carry = scan_chunk(b, rowout, k + 1, l, kE, kL, carry);
        }
    }
}

extern "C" void kernel_launch(void* const* d_in, const int* in_sizes, int n_in,
                              void* d_out, int out_size)
{
    const float* c    = (const float*)d_in[0];
    const float* beta = (const float*)d_in[1];
    float* out        = (float*)d_out;

    const int nrows = in_sizes[0] / S_LEN;   // 4096

    reset_ticket_kernel<<<1, 1>>>();
    softmaxplus_scan_kernel<<<GRID, NTHREADS>>>(c, beta, out, nrows);
}

// round 8
// speedup vs baseline: 1.8527x; 1.0069x over previous
#include <cuda_runtime.h>

// SoftMaxPlus: out[b, :] = cumsum(softplus(beta * c[b, :]) / beta) along S.
// B=4096 rows, S=8192 cols, fp32.
// Warp-autonomous + cp.async smem ring:
//   each warp owns one row (atomic ticket), private 3-slot x 2KB smem ring,
//   fetch cursor runs ahead of scan cursor ACROSS row boundaries (no drain).
// No CTA barriers. All cp.async/LDS/STG fully coalesced / conflict-free.

constexpr int S_LEN    = 8192;
constexpr int NTHREADS = 512;           // 16 warps
constexpr int NWARPS   = 16;
constexpr int CHUNK    = 512;           // floats per chunk (2KB)
constexpr int NCHUNK   = S_LEN / CHUNK; // 16
constexpr int DEPTH    = 3;             // ring slots per warp
constexpr int GRID     = 304;           // 152 SMs x 2 CTAs

__device__ unsigned g_ticket;
__global__ void reset_ticket_kernel() { g_ticket = 0u; }

__device__ __forceinline__ void cp16(float* smem_dst, const float* gsrc)
{
    unsigned s = (unsigned)__cvta_generic_to_shared(smem_dst);
    asm volatile("cp.async.cg.shared.global [%0], [%1], 16;\n" :: "r"(s), "l"(gsrc));
}

// Prefetch one 512-float chunk into a ring slot (4 coalesced 16B per lane).
// Always commits exactly one group (even when invalid) to keep counts aligned.
__device__ __forceinline__ void prefetch_chunk(float* slot, const float* __restrict__ c,
                                               unsigned row, int k, int nrows, int l)
{
    if (row < (unsigned)nrows) {
        const float* src = c + (long long)row * S_LEN + k * CHUNK;
#pragma unroll
        for (int j = 0; j < 4; j++) {
            const int idx = j * 128 + l * 4;
            cp16(slot + idx, src + idx);
        }
    }
    asm volatile("cp.async.commit_group;\n" ::: "memory");
}

// softplus(beta*c)/beta = max(c,0) + log2(1 + exp2(kE*|c|)) * kL
__device__ __forceinline__ float sp_fast(float c, float kE, float kL)
{
    float t = exp2f(kE * fabsf(c));
    return fmaxf(c, 0.0f) + __log2f(1.0f + t) * kL;
}

extern __shared__ float ring[];   // NWARPS * DEPTH * CHUNK floats (96 KB)

__global__ __launch_bounds__(NTHREADS, 2)
void softmaxplus_scan_kernel(const float* __restrict__ c,
                             const float* __restrict__ beta_ptr,
                             float* __restrict__ out,
                             int nrows)
{
    const int w = threadIdx.x >> 5;
    const int l = threadIdx.x & 31;
    float* myring = ring + (w * DEPTH) * CHUNK;

    const float beta = __ldg(beta_ptr);
    const float kE = -beta * 1.4426950408889634f;    // -beta*log2(e)
    const float kL = 0.6931471805599453f / beta;     // ln2/beta

    // ---- ticket helper (lane 0 atomics, broadcast) ----
    auto ticket = [&]() -> unsigned {
        unsigned r = 0u;
        if (l == 0) r = atomicAdd(&g_ticket, 1u);
        return __shfl_sync(0xFFFFFFFFu, r, 0);
    };

    // scan cursor: row q0, chunk kS.  fetch cursor: row rowF, chunk kF.
    unsigned q0 = ticket();
    unsigned q1 = q0;            // next row after q0 (filled when fetch crosses)
    unsigned rowF = q0;
    int kF = 0;

    auto advanceF = [&]() {
        if (++kF == NCHUNK) {
            kF = 0;
            q1 = ticket();
            rowF = q1;
        }
    };

    // ---- prologue: fill the ring ----
#pragma unroll
    for (int d = 0; d < DEPTH; d++) {
        prefetch_chunk(myring + d * CHUNK, c, rowF, kF, nrows, l);
        advanceF();
    }

    int slot = 0;
    int kS = 0;
    float carry = 0.0f;

    while (q0 < (unsigned)nrows) {
        asm volatile("cp.async.wait_group %0;\n" :: "n"(DEPTH - 1) : "memory");

        const float* sbuf = myring + slot * CHUNK;
        float4 v[4];
#pragma unroll
        for (int j = 0; j < 4; j++)
            v[j] = *reinterpret_cast<const float4*>(sbuf + j * 128 + l * 4);

        // slot consumed into registers -> reuse for the fetch cursor
        prefetch_chunk(myring + slot * CHUNK, c, rowF, kF, nrows, l);
        advanceF();

        // ---- scan this chunk ----
        float gt[4], tx[4];
#pragma unroll
        for (int j = 0; j < 4; j++) {
            float f0 = sp_fast(v[j].x, kE, kL);
            float f1 = sp_fast(v[j].y, kE, kL);
            float f2 = sp_fast(v[j].z, kE, kL);
            float f3 = sp_fast(v[j].w, kE, kL);
            v[j].x = f0;
            v[j].y = v[j].x + f1;
            v[j].z = v[j].y + f2;
            v[j].w = v[j].z + f3;
            float ws = v[j].w;
#pragma unroll
            for (int o = 1; o < 32; o <<= 1) {
                float y = __shfl_up_sync(0xFFFFFFFFu, ws, o);
                if (l >= o) ws += y;
            }
            tx[j] = ws - v[j].w;                       // exclusive in-segment
            gt[j] = __shfl_sync(0xFFFFFFFFu, ws, 31);  // segment total
        }

        float* rowout = out + (long long)q0 * S_LEN + kS * CHUNK;
        float e = carry;
#pragma unroll
        for (int j = 0; j < 4; j++) {
            const float o = e + tx[j];
            float4 r = make_float4(v[j].x + o, v[j].y + o, v[j].z + o, v[j].w + o);
            __stcs(reinterpret_cast<float4*>(rowout + j * 128 + l * 4), r);
            e += gt[j];
        }
        carry = e;

        if (++kS == NCHUNK) {     // row finished
            kS = 0;
            carry = 0.0f;
            q0 = q1;              // fetch already moved to this row
        }
        slot = (slot == DEPTH - 1) ? 0 : slot + 1;
    }
}

extern "C" void kernel_launch(void* const* d_in, const int* in_sizes, int n_in,
                              void* d_out, int out_size)
{
    const float* c    = (const float*)d_in[0];
    const float* beta = (const float*)d_in[1];
    float* out        = (float*)d_out;

    const int nrows = in_sizes[0] / S_LEN;   // 4096
    const int smem_bytes = NWARPS * DEPTH * CHUNK * sizeof(float);  // 96 KB

    static bool attr_set = false;
    if (!attr_set) {
        cudaFuncSetAttribute(softmaxplus_scan_kernel,
                             cudaFuncAttributeMaxDynamicSharedMemorySize, smem_bytes);
        attr_set = true;
    }

    reset_ticket_kernel<<<1, 1>>>();
    softmaxplus_scan_kernel<<<GRID, NTHREADS, smem_bytes>>>(c, beta, out, nrows);
}

// round 9
// speedup vs baseline: 1.9960x; 1.0773x over previous
#include <cuda_runtime.h>

// SoftMaxPlus: out[b, :] = cumsum(softplus(beta * c[b, :]) / beta) along S.
// B=4096 rows, S=8192 cols, fp32.
// CTA-per-row (minimizes concurrent DRAM streams: ~304 read + ~304 write),
// ticket-balanced via a smem row-id queue refilled one ticket/iteration,
// depth-3 cp.async ring with cross-row fetch-ahead (never drains).
// Each thread async-copies exactly the bytes it later reads -> per-thread
// wait_group suffices; the one per-row __syncthreads doubles as the publish
// point for both the row queue and the warp totals.

constexpr int S_LEN    = 8192;
constexpr int NTHREADS = 512;
constexpr int NWARPS   = 16;
constexpr int GROUPS   = 4;      // 4 float4 segments per thread
constexpr int DEPTH    = 3;      // ring depth (rows)
constexpr int QN       = 8;      // row-id queue size (> 2*DEPTH, power of 2)
constexpr int GRID     = 304;    // 152 SMs x 2 CTAs

__device__ unsigned g_ticket;
__global__ void reset_ticket_kernel() { g_ticket = 0u; }

__device__ __forceinline__ void cp16(float* smem_dst, const float* gsrc)
{
    unsigned s = (unsigned)__cvta_generic_to_shared(smem_dst);
    asm volatile("cp.async.cg.shared.global [%0], [%1], 16;\n" :: "r"(s), "l"(gsrc));
}

// Prefetch one full row into a ring slot. Always commits exactly one group.
__device__ __forceinline__ void prefetch_row(float* slot, const float* __restrict__ c,
                                             unsigned row, int nrows, int w, int l)
{
    if (row < (unsigned)nrows) {
        const float* src = c + (long long)row * S_LEN;
#pragma unroll
        for (int g = 0; g < GROUPS; g++) {
            const int idx = ((w * GROUPS + g) * 32 + l) * 4;
            cp16(slot + idx, src + idx);
        }
    }
    asm volatile("cp.async.commit_group;\n" ::: "memory");
}

// softplus(beta*c)/beta = max(c,0) + log2(1 + exp2(kE*|c|)) * kL
__device__ __forceinline__ float sp_fast(float c, float kE, float kL)
{
    float t = exp2f(kE * fabsf(c));
    return fmaxf(c, 0.0f) + __log2f(1.0f + t) * kL;
}

extern __shared__ float ring[];            // DEPTH * S_LEN floats (96 KB)

__global__ __launch_bounds__(NTHREADS, 2)
void softmaxplus_scan_kernel(const float* __restrict__ c,
                             const float* __restrict__ beta_ptr,
                             float* __restrict__ out,
                             int nrows)
{
    __shared__ unsigned rowq[QN];
    __shared__ float    tot[2][NWARPS];

    const int t = threadIdx.x;
    const int w = t >> 5;
    const int l = t & 31;

    const float beta = __ldg(beta_ptr);
    const float kE = -beta * 1.4426950408889634f;    // -beta*log2(e)
    const float kL = 0.6931471805599453f / beta;     // ln2/beta

    // ---- prologue: pull DEPTH tickets, publish, fill the ring ----
    if (t == 0) {
#pragma unroll
        for (int d = 0; d < DEPTH; d++) rowq[d] = atomicAdd(&g_ticket, 1u);
    }
    __syncthreads();
#pragma unroll
    for (int d = 0; d < DEPTH; d++)
        prefetch_row(ring + d * S_LEN, c, rowq[d], nrows, w, l);

    int it = 0;
    for (;;) {
        const unsigned row = rowq[it & (QN - 1)];    // published >= DEPTH iters ago
        if (row >= (unsigned)nrows) {
            asm volatile("cp.async.wait_all;\n" ::: "memory");
            break;
        }

        asm volatile("cp.async.wait_group %0;\n" :: "n"(DEPTH - 1) : "memory");

        const int slot = it % DEPTH;
        const float* sbuf = ring + slot * S_LEN;

        // ---- read own 16 floats from smem ----
        float4 vv[GROUPS];
#pragma unroll
        for (int g = 0; g < GROUPS; g++)
            vv[g] = *reinterpret_cast<const float4*>(sbuf + ((w * GROUPS + g) * 32 + l) * 4);

        // pull next ticket (published by this iteration's barrier)
        if (t == 0) rowq[(it + DEPTH) & (QN - 1)] = atomicAdd(&g_ticket, 1u);

        // ---- elementwise + per-thread prefix + segment warp scans ----
        float p[GROUPS][4], texcl[GROUPS], gtot[GROUPS];
#pragma unroll
        for (int g = 0; g < GROUPS; g++) {
            float f0 = sp_fast(vv[g].x, kE, kL);
            float f1 = sp_fast(vv[g].y, kE, kL);
            float f2 = sp_fast(vv[g].z, kE, kL);
            float f3 = sp_fast(vv[g].w, kE, kL);
            p[g][0] = f0;
            p[g][1] = p[g][0] + f1;
            p[g][2] = p[g][1] + f2;
            p[g][3] = p[g][2] + f3;
            float ws = p[g][3];
#pragma unroll
            for (int o = 1; o < 32; o <<= 1) {
                float y = __shfl_up_sync(0xFFFFFFFFu, ws, o);
                if (l >= o) ws += y;
            }
            texcl[g] = ws - p[g][3];
            gtot[g]  = __shfl_sync(0xFFFFFFFFu, ws, 31);
        }

        const float ge1 = gtot[0];
        const float ge2 = ge1 + gtot[1];
        const float ge3 = ge2 + gtot[2];
        const float wtot = ge3 + gtot[3];

        float* tb = tot[it & 1];
        if (l == 0) tb[w] = wtot;
        __syncthreads();   // publishes warp totals AND the new rowq entry

        // refill the consumed slot for the row fetched DEPTH ahead
        prefetch_row(ring + slot * S_LEN, c, rowq[(it + DEPTH) & (QN - 1)], nrows, w, l);

        // exclusive sum of warp totals for warps < w (masked butterfly)
        float m = (l < w) ? tb[l] : 0.0f;
#pragma unroll
        for (int o = 16; o >= 1; o >>= 1)
            m += __shfl_xor_sync(0xFFFFFFFFu, m, o);

        const float offs[GROUPS] = {m, m + ge1, m + ge2, m + ge3};

        float* rowout = out + (long long)row * S_LEN;
#pragma unroll
        for (int g = 0; g < GROUPS; g++) {
            const float o = offs[g] + texcl[g];
            float4 r = make_float4(p[g][0] + o, p[g][1] + o, p[g][2] + o, p[g][3] + o);
            __stcs(reinterpret_cast<float4*>(rowout + ((w * GROUPS + g) * 32 + l) * 4), r);
        }

        it++;
    }
}

extern "C" void kernel_launch(void* const* d_in, const int* in_sizes, int n_in,
                              void* d_out, int out_size)
{
    const float* c    = (const float*)d_in[0];
    const float* beta = (const float*)d_in[1];
    float* out        = (float*)d_out;

    const int nrows = in_sizes[0] / S_LEN;   // 4096
    const int smem_bytes = DEPTH * S_LEN * sizeof(float);  // 96 KB

    static bool attr_set = false;
    if (!attr_set) {
        cudaFuncSetAttribute(softmaxplus_scan_kernel,
                             cudaFuncAttributeMaxDynamicSharedMemorySize, smem_bytes);
        attr_set = true;
    }

    reset_ticket_kernel<<<1, 1>>>();
    softmaxplus_scan_kernel<<<GRID, NTHREADS, smem_bytes>>>(c, beta, out, nrows);
}